// round 15
// baseline (speedup 1.0000x reference)
#include <cuda_runtime.h>
#include <cuda_fp16.h>
#include <cstdint>
#include <cstddef>

// ---------------------------------------------------------------------------
// R8 configuration (verified 670.5/670.5/670.3 us) + k_abs MLP batching.
//   x -> fp16 (rel_err 2.08e-4, 4.8x under gate), w -> ternary fp16 (exact),
//   GEMM via legacy mma.sync m16n8k16 f16 at the sm_103/compute_103 HMMA floor.
// ---------------------------------------------------------------------------
#define M_DIM 8192
#define N_DIM 4096
#define K_DIM 4096

// GEMM tiling
#define BM 128
#define BN 256
#define BK 64                    // fp16 elems per K-tile = 128 bytes/row
#define STAGES 4
#define KT (K_DIM / BK)          // 64
#define GEMM_THREADS 256         // 8 warps: 2 (M) x 4 (N), warp tile 64x64

#define A_TILE_BYTES (BM * 128)                    // 16 KB
#define B_TILE_BYTES (BN * 128)                    // 32 KB
#define STAGE_BYTES  (A_TILE_BYTES + B_TILE_BYTES) // 48 KB
#define SMEM_TOTAL   (STAGES * STAGE_BYTES)        // 192 KB

#define ABS_BLOCKS   1024        // k1: |w| partials -> w L2-resident
#define QUANT_BLOCKS 2048        // k2: quantize w first (L2-hot)
#define CONV_BLOCKS  8192        // k2: convert x

// ---------------------------------------------------------------------------
// Device scratch (allocation-free rule: __device__ globals)
// ---------------------------------------------------------------------------
__device__ float g_partials[ABS_BLOCKS];
__device__ __align__(1024) __half g_q [(size_t)N_DIM * K_DIM]; // 32 MB {-1,0,1} exact
__device__ __align__(1024) __half g_xh[(size_t)M_DIM * K_DIM]; // 64 MB x in fp16

// ---------------------------------------------------------------------------
// Helpers
// ---------------------------------------------------------------------------
__device__ __forceinline__ uint32_t smem_u32(const void* p) {
    return (uint32_t)__cvta_generic_to_shared(p);
}

__device__ __forceinline__ void cp16(uint32_t dst, const void* src) {
    asm volatile("cp.async.cg.shared.global [%0], [%1], 16;" :: "r"(dst), "l"(src));
}

__device__ __forceinline__ void ldsm_x4(uint32_t (&r)[4], uint32_t addr) {
    asm volatile("ldmatrix.sync.aligned.m8n8.x4.shared.b16 {%0,%1,%2,%3}, [%4];"
                 : "=r"(r[0]), "=r"(r[1]), "=r"(r[2]), "=r"(r[3]) : "r"(addr));
}

__device__ __forceinline__ void mma16816(float (&c)[4], const uint32_t (&a)[4],
                                         uint32_t b0, uint32_t b1) {
    asm volatile(
        "mma.sync.aligned.m16n8k16.row.col.f32.f16.f16.f32 "
        "{%0,%1,%2,%3}, {%4,%5,%6,%7}, {%8,%9}, {%0,%1,%2,%3};"
        : "+f"(c[0]), "+f"(c[1]), "+f"(c[2]), "+f"(c[3])
        : "r"(a[0]), "r"(a[1]), "r"(a[2]), "r"(a[3]), "r"(b0), "r"(b1));
}

__device__ __forceinline__ uint32_t pack2h(float a, float b) {
    __half2 t = __floats2half2_rn(a, b);
    union { __half2 h; uint32_t u; } cv;
    cv.h = t;
    return cv.u;
}

// ---------------------------------------------------------------------------
// k1: |w| partial sums, MLP-batched: 4 independent LDG.128 in flight per
//     thread per iteration (front-batched loads, then reduce).
//     Leaves w L2-resident (64 MB < 126 MB L2).
// ---------------------------------------------------------------------------
__global__ void k_abs(const float* __restrict__ w) {
    const float4* w4 = (const float4*)w;
    const int n4 = (N_DIM * K_DIM) / 4;          // 4,194,304
    const int stride = ABS_BLOCKS * 256;         // 262,144
    // n4 / stride = 16 iterations -> 4 batched iterations of 4 loads
    float s = 0.0f;
    int i = blockIdx.x * 256 + threadIdx.x;
    #pragma unroll
    for (int b = 0; b < 4; b++) {
        float4 v0 = w4[i];
        float4 v1 = w4[i + stride];
        float4 v2 = w4[i + 2 * stride];
        float4 v3 = w4[i + 3 * stride];
        s += fabsf(v0.x) + fabsf(v0.y) + fabsf(v0.z) + fabsf(v0.w);
        s += fabsf(v1.x) + fabsf(v1.y) + fabsf(v1.z) + fabsf(v1.w);
        s += fabsf(v2.x) + fabsf(v2.y) + fabsf(v2.z) + fabsf(v2.w);
        s += fabsf(v3.x) + fabsf(v3.y) + fabsf(v3.z) + fabsf(v3.w);
        i += 4 * stride;
    }
    __shared__ float sm[256];
    sm[threadIdx.x] = s;
    __syncthreads();
    for (int o = 128; o > 0; o >>= 1) {
        if (threadIdx.x < o) sm[threadIdx.x] += sm[threadIdx.x + o];
        __syncthreads();
    }
    if (threadIdx.x == 0) g_partials[blockIdx.x] = sm[0];
}

// ---------------------------------------------------------------------------
// k2: blocks [0,QUANT_BLOCKS) re-reduce partials (deterministic fixed-order
//     tree, identical per block), then quantize w -> fp16 {-1,0,1} while w is
//     still L2-hot. blocks [QUANT_BLOCKS,+CONV_BLOCKS) convert x -> fp16.
// ---------------------------------------------------------------------------
__global__ void k_prep2(const float* __restrict__ w, const float* __restrict__ x) {
    if (blockIdx.x < QUANT_BLOCKS) {
        __shared__ float sm[256];
        {
            float s = 0.0f;
            #pragma unroll
            for (int j = 0; j < ABS_BLOCKS / 256; j++)
                s += g_partials[threadIdx.x * (ABS_BLOCKS / 256) + j];
            sm[threadIdx.x] = s;
            __syncthreads();
            for (int o = 128; o > 0; o >>= 1) {
                if (threadIdx.x < o) sm[threadIdx.x] += sm[threadIdx.x + o];
                __syncthreads();
            }
        }
        const float thr = 0.05f * (sm[0] / (float)((size_t)N_DIM * K_DIM));

        const float4* w4 = (const float4*)w;
        uint2* q4 = (uint2*)g_q;
        const int n4 = (N_DIM * K_DIM) / 4;
        auto tq = [&](float v) -> float {
            return v > thr ? 1.0f : (v < -thr ? -1.0f : 0.0f);
        };
        for (int i = blockIdx.x * blockDim.x + threadIdx.x; i < n4;
             i += QUANT_BLOCKS * blockDim.x) {
            float4 v = w4[i];
            uint2 o;
            o.x = pack2h(tq(v.x), tq(v.y));
            o.y = pack2h(tq(v.z), tq(v.w));
            q4[i] = o;
        }
    } else {
        const int bid = blockIdx.x - QUANT_BLOCKS;
        const float4* x4 = (const float4*)x;
        uint2* h4 = (uint2*)g_xh;
        const int n4 = (M_DIM * K_DIM) / 4;
        for (int i = bid * blockDim.x + threadIdx.x; i < n4;
             i += CONV_BLOCKS * blockDim.x) {
            float4 v = x4[i];
            uint2 o;
            o.x = pack2h(v.x, v.y);
            o.y = pack2h(v.z, v.w);
            h4[i] = o;
        }
    }
}

// ---------------------------------------------------------------------------
// GEMM: out = x_fp16 @ q^T via mma.sync m16n8k16 f16 (fp32 accum)
//   CTA tile 128x256, warp tile 64x64, 4-stage cp.async pipeline.
//   Proven floor on this build target — do not touch.
// ---------------------------------------------------------------------------
__global__ void __launch_bounds__(GEMM_THREADS, 1)
k_gemm(float* __restrict__ out) {
    extern __shared__ char smem[];
    const uint32_t sb = smem_u32(smem);
    const int tid  = threadIdx.x;
    const int wid  = tid >> 5;
    const int lane = tid & 31;
    const int warp_m = wid & 1;   // 64 rows each
    const int warp_n = wid >> 1;  // 64 cols each
    const int m0 = blockIdx.y * BM;
    const int n0 = blockIdx.x * BN;

    // ---- async tile loader (XOR-swizzled 16B chunks, 128B rows) ----
    auto load_stage = [&](int kt, int st) {
        const uint32_t base = sb + st * STAGE_BYTES;
        const size_t kofs = (size_t)kt * BK;
        #pragma unroll
        for (int i = tid; i < BM * 8; i += GEMM_THREADS) {
            const int r = i >> 3, c = i & 7;
            const uint32_t d = base + r * 128 + ((c ^ (r & 7)) << 4);
            cp16(d, &g_xh[(size_t)(m0 + r) * K_DIM + kofs + c * 8]);
        }
        #pragma unroll
        for (int i = tid; i < BN * 8; i += GEMM_THREADS) {
            const int r = i >> 3, c = i & 7;
            const uint32_t d = base + A_TILE_BYTES + r * 128 + ((c ^ (r & 7)) << 4);
            cp16(d, &g_q[(size_t)(n0 + r) * K_DIM + kofs + c * 8]);
        }
        asm volatile("cp.async.commit_group;" ::: "memory");
    };

    float acc[4][8][4];   // 128 regs
    #pragma unroll
    for (int mi = 0; mi < 4; mi++)
        #pragma unroll
        for (int ni = 0; ni < 8; ni++)
            #pragma unroll
            for (int j = 0; j < 4; j++) acc[mi][ni][j] = 0.0f;

    // ldmatrix lane addressing (verified layout)
    const int a_row  = warp_m * 64 + (lane & 15);
    const int a_half = lane >> 4;
    const int b_row  = warp_n * 64 + (lane & 7) + ((lane >> 4) << 3);
    const int b_half = (lane >> 3) & 1;

    #pragma unroll
    for (int j = 0; j < STAGES - 1; j++) load_stage(j, j);

    for (int it = 0; it < KT; it++) {
        const int st = it % STAGES;
        asm volatile("cp.async.wait_group %0;" :: "n"(STAGES - 2) : "memory");
        __syncthreads();

        const uint32_t abase = sb + st * STAGE_BYTES;
        const uint32_t bbase = abase + A_TILE_BYTES;

        #pragma unroll
        for (int ks = 0; ks < 4; ks++) {  // 4 x k16 covers BK=64
            // B frags: 4 ldsm.x4 -> 8 n8-frags
            uint32_t bfr[8][2];
            #pragma unroll
            for (int jt = 0; jt < 4; jt++) {
                const int n = b_row + jt * 16;
                const int ch = ks * 2 + b_half;
                uint32_t r4[4];
                ldsm_x4(r4, bbase + n * 128 + ((ch ^ (n & 7)) << 4));
                bfr[2 * jt + 0][0] = r4[0]; bfr[2 * jt + 0][1] = r4[1];
                bfr[2 * jt + 1][0] = r4[2]; bfr[2 * jt + 1][1] = r4[3];
            }
            // A frags + MMA
            #pragma unroll
            for (int mi = 0; mi < 4; mi++) {
                const int r = a_row + mi * 16;
                const int ch = ks * 2 + a_half;
                uint32_t a4[4];
                ldsm_x4(a4, abase + r * 128 + ((ch ^ (r & 7)) << 4));
                #pragma unroll
                for (int ni = 0; ni < 8; ni++)
                    mma16816(acc[mi][ni], a4, bfr[ni][0], bfr[ni][1]);
            }
        }

        if (it + STAGES - 1 < KT) load_stage(it + STAGES - 1, (it + STAGES - 1) % STAGES);
        else asm volatile("cp.async.commit_group;" ::: "memory");
    }

    // ---- epilogue: streaming float2 stores (out never re-read) ----
    const int er = lane >> 2;
    const int ec = (lane & 3) * 2;
    #pragma unroll
    for (int mi = 0; mi < 4; mi++) {
        #pragma unroll
        for (int ni = 0; ni < 8; ni++) {
            const int row = m0 + warp_m * 64 + mi * 16 + er;
            const int col = n0 + warp_n * 64 + ni * 8 + ec;
            float2 v0 = make_float2(acc[mi][ni][0], acc[mi][ni][1]);
            float2 v1 = make_float2(acc[mi][ni][2], acc[mi][ni][3]);
            __stcs((float2*)&out[(size_t)row * N_DIM + col], v0);
            __stcs((float2*)&out[(size_t)(row + 8) * N_DIM + col], v1);
        }
    }
}

// ---------------------------------------------------------------------------
// Launch
// ---------------------------------------------------------------------------
extern "C" void kernel_launch(void* const* d_in, const int* in_sizes, int n_in,
                              void* d_out, int out_size) {
    const float* x = (const float*)d_in[0];   // [8192, 4096]
    const float* w = (const float*)d_in[1];   // [4096, 4096]
    float* out = (float*)d_out;               // [8192, 4096]

    cudaFuncSetAttribute(k_gemm, cudaFuncAttributeMaxDynamicSharedMemorySize, SMEM_TOTAL);

    k_abs<<<ABS_BLOCKS, 256>>>(w);                      // w -> L2-resident
    k_prep2<<<QUANT_BLOCKS + CONV_BLOCKS, 256>>>(w, x); // quant (L2-hot) + convert

    // N-blocks fast: a concurrent wave shares q (32 MB, L2-resident)
    dim3 grid(N_DIM / BN, M_DIM / BM);
    k_gemm<<<grid, GEMM_THREADS, SMEM_TOTAL>>>(out);
}

// round 16
// speedup vs baseline: 1.0011x; 1.0011x over previous
#include <cuda_runtime.h>
#include <cuda_fp16.h>
#include <cstdint>
#include <cstddef>

// ---------------------------------------------------------------------------
// FINAL (converged, verified 670.5/670.5/670.3 us): R8 configuration.
//   x -> fp16 (rel_err 2.08e-4, 4.8x under gate), w -> ternary fp16 (exact),
//   GEMM via legacy mma.sync m16n8k16 f16 at the sm_103/compute_103 HMMA floor.
// Session evidence (why nothing else is left):
//   - tcgen05 unreachable: virtual arch compute_103 rejects all "a" features (R1)
//   - int8 legacy IMMA ~6x slower per instruction than HMMA here (R3)
//   - GEMM mainloop floor 612 us: R5 warp-split, R6 stage-depth, R7 reg
//     double-buffer, R13 sync-loader all neutral or worse
//   - prep floor ~58 us: R6/R8/R9/R10/R11 arrangements within noise
//   - async g_xh round-trip is load-bearing: removing it cost +290 us (R13)
//   - k_abs is launch/ramp-bound at 14 us: R9 and R15 both neutral/worse
// ---------------------------------------------------------------------------
#define M_DIM 8192
#define N_DIM 4096
#define K_DIM 4096

// GEMM tiling
#define BM 128
#define BN 256
#define BK 64                    // fp16 elems per K-tile = 128 bytes/row
#define STAGES 4
#define KT (K_DIM / BK)          // 64
#define GEMM_THREADS 256         // 8 warps: 2 (M) x 4 (N), warp tile 64x64

#define A_TILE_BYTES (BM * 128)                    // 16 KB
#define B_TILE_BYTES (BN * 128)                    // 32 KB
#define STAGE_BYTES  (A_TILE_BYTES + B_TILE_BYTES) // 48 KB
#define SMEM_TOTAL   (STAGES * STAGE_BYTES)        // 192 KB

#define ABS_BLOCKS   1024        // k1: |w| partials -> w L2-resident
#define QUANT_BLOCKS 2048        // k2: quantize w first (L2-hot)
#define CONV_BLOCKS  8192        // k2: convert x

// ---------------------------------------------------------------------------
// Device scratch (allocation-free rule: __device__ globals)
// ---------------------------------------------------------------------------
__device__ float g_partials[ABS_BLOCKS];
__device__ __align__(1024) __half g_q [(size_t)N_DIM * K_DIM]; // 32 MB {-1,0,1} exact
__device__ __align__(1024) __half g_xh[(size_t)M_DIM * K_DIM]; // 64 MB x in fp16

// ---------------------------------------------------------------------------
// Helpers
// ---------------------------------------------------------------------------
__device__ __forceinline__ uint32_t smem_u32(const void* p) {
    return (uint32_t)__cvta_generic_to_shared(p);
}

__device__ __forceinline__ void cp16(uint32_t dst, const void* src) {
    asm volatile("cp.async.cg.shared.global [%0], [%1], 16;" :: "r"(dst), "l"(src));
}

__device__ __forceinline__ void ldsm_x4(uint32_t (&r)[4], uint32_t addr) {
    asm volatile("ldmatrix.sync.aligned.m8n8.x4.shared.b16 {%0,%1,%2,%3}, [%4];"
                 : "=r"(r[0]), "=r"(r[1]), "=r"(r[2]), "=r"(r[3]) : "r"(addr));
}

__device__ __forceinline__ void mma16816(float (&c)[4], const uint32_t (&a)[4],
                                         uint32_t b0, uint32_t b1) {
    asm volatile(
        "mma.sync.aligned.m16n8k16.row.col.f32.f16.f16.f32 "
        "{%0,%1,%2,%3}, {%4,%5,%6,%7}, {%8,%9}, {%0,%1,%2,%3};"
        : "+f"(c[0]), "+f"(c[1]), "+f"(c[2]), "+f"(c[3])
        : "r"(a[0]), "r"(a[1]), "r"(a[2]), "r"(a[3]), "r"(b0), "r"(b1));
}

__device__ __forceinline__ uint32_t pack2h(float a, float b) {
    __half2 t = __floats2half2_rn(a, b);
    union { __half2 h; uint32_t u; } cv;
    cv.h = t;
    return cv.u;
}

// ---------------------------------------------------------------------------
// k1: |w| partial sums only (leaves w L2-resident: 64 MB < 126 MB L2)
// ---------------------------------------------------------------------------
__global__ void k_abs(const float* __restrict__ w) {
    const float4* w4 = (const float4*)w;
    const int n4 = (N_DIM * K_DIM) / 4;
    float s = 0.0f;
    for (int i = blockIdx.x * blockDim.x + threadIdx.x; i < n4;
         i += ABS_BLOCKS * blockDim.x) {
        float4 v = w4[i];
        s += fabsf(v.x) + fabsf(v.y) + fabsf(v.z) + fabsf(v.w);
    }
    __shared__ float sm[256];
    sm[threadIdx.x] = s;
    __syncthreads();
    for (int o = 128; o > 0; o >>= 1) {
        if (threadIdx.x < o) sm[threadIdx.x] += sm[threadIdx.x + o];
        __syncthreads();
    }
    if (threadIdx.x == 0) g_partials[blockIdx.x] = sm[0];
}

// ---------------------------------------------------------------------------
// k2: blocks [0,QUANT_BLOCKS) re-reduce partials (deterministic fixed-order
//     tree, identical per block), then quantize w -> fp16 {-1,0,1} while w is
//     still L2-hot. blocks [QUANT_BLOCKS,+CONV_BLOCKS) convert x -> fp16.
// ---------------------------------------------------------------------------
__global__ void k_prep2(const float* __restrict__ w, const float* __restrict__ x) {
    if (blockIdx.x < QUANT_BLOCKS) {
        __shared__ float sm[256];
        {
            float s = 0.0f;
            #pragma unroll
            for (int j = 0; j < ABS_BLOCKS / 256; j++)
                s += g_partials[threadIdx.x * (ABS_BLOCKS / 256) + j];
            sm[threadIdx.x] = s;
            __syncthreads();
            for (int o = 128; o > 0; o >>= 1) {
                if (threadIdx.x < o) sm[threadIdx.x] += sm[threadIdx.x + o];
                __syncthreads();
            }
        }
        const float thr = 0.05f * (sm[0] / (float)((size_t)N_DIM * K_DIM));

        const float4* w4 = (const float4*)w;
        uint2* q4 = (uint2*)g_q;
        const int n4 = (N_DIM * K_DIM) / 4;
        auto tq = [&](float v) -> float {
            return v > thr ? 1.0f : (v < -thr ? -1.0f : 0.0f);
        };
        for (int i = blockIdx.x * blockDim.x + threadIdx.x; i < n4;
             i += QUANT_BLOCKS * blockDim.x) {
            float4 v = w4[i];
            uint2 o;
            o.x = pack2h(tq(v.x), tq(v.y));
            o.y = pack2h(tq(v.z), tq(v.w));
            q4[i] = o;
        }
    } else {
        const int bid = blockIdx.x - QUANT_BLOCKS;
        const float4* x4 = (const float4*)x;
        uint2* h4 = (uint2*)g_xh;
        const int n4 = (M_DIM * K_DIM) / 4;
        for (int i = bid * blockDim.x + threadIdx.x; i < n4;
             i += CONV_BLOCKS * blockDim.x) {
            float4 v = x4[i];
            uint2 o;
            o.x = pack2h(v.x, v.y);
            o.y = pack2h(v.z, v.w);
            h4[i] = o;
        }
    }
}

// ---------------------------------------------------------------------------
// GEMM: out = x_fp16 @ q^T via mma.sync m16n8k16 f16 (fp32 accum)
//   CTA tile 128x256, warp tile 64x64, 4-stage cp.async pipeline.
//   Proven floor on this build target — do not touch.
// ---------------------------------------------------------------------------
__global__ void __launch_bounds__(GEMM_THREADS, 1)
k_gemm(float* __restrict__ out) {
    extern __shared__ char smem[];
    const uint32_t sb = smem_u32(smem);
    const int tid  = threadIdx.x;
    const int wid  = tid >> 5;
    const int lane = tid & 31;
    const int warp_m = wid & 1;   // 64 rows each
    const int warp_n = wid >> 1;  // 64 cols each
    const int m0 = blockIdx.y * BM;
    const int n0 = blockIdx.x * BN;

    // ---- async tile loader (XOR-swizzled 16B chunks, 128B rows) ----
    auto load_stage = [&](int kt, int st) {
        const uint32_t base = sb + st * STAGE_BYTES;
        const size_t kofs = (size_t)kt * BK;
        #pragma unroll
        for (int i = tid; i < BM * 8; i += GEMM_THREADS) {
            const int r = i >> 3, c = i & 7;
            const uint32_t d = base + r * 128 + ((c ^ (r & 7)) << 4);
            cp16(d, &g_xh[(size_t)(m0 + r) * K_DIM + kofs + c * 8]);
        }
        #pragma unroll
        for (int i = tid; i < BN * 8; i += GEMM_THREADS) {
            const int r = i >> 3, c = i & 7;
            const uint32_t d = base + A_TILE_BYTES + r * 128 + ((c ^ (r & 7)) << 4);
            cp16(d, &g_q[(size_t)(n0 + r) * K_DIM + kofs + c * 8]);
        }
        asm volatile("cp.async.commit_group;" ::: "memory");
    };

    float acc[4][8][4];   // 128 regs
    #pragma unroll
    for (int mi = 0; mi < 4; mi++)
        #pragma unroll
        for (int ni = 0; ni < 8; ni++)
            #pragma unroll
            for (int j = 0; j < 4; j++) acc[mi][ni][j] = 0.0f;

    // ldmatrix lane addressing (verified layout)
    const int a_row  = warp_m * 64 + (lane & 15);
    const int a_half = lane >> 4;
    const int b_row  = warp_n * 64 + (lane & 7) + ((lane >> 4) << 3);
    const int b_half = (lane >> 3) & 1;

    #pragma unroll
    for (int j = 0; j < STAGES - 1; j++) load_stage(j, j);

    for (int it = 0; it < KT; it++) {
        const int st = it % STAGES;
        asm volatile("cp.async.wait_group %0;" :: "n"(STAGES - 2) : "memory");
        __syncthreads();

        const uint32_t abase = sb + st * STAGE_BYTES;
        const uint32_t bbase = abase + A_TILE_BYTES;

        #pragma unroll
        for (int ks = 0; ks < 4; ks++) {  // 4 x k16 covers BK=64
            // B frags: 4 ldsm.x4 -> 8 n8-frags
            uint32_t bfr[8][2];
            #pragma unroll
            for (int jt = 0; jt < 4; jt++) {
                const int n = b_row + jt * 16;
                const int ch = ks * 2 + b_half;
                uint32_t r4[4];
                ldsm_x4(r4, bbase + n * 128 + ((ch ^ (n & 7)) << 4));
                bfr[2 * jt + 0][0] = r4[0]; bfr[2 * jt + 0][1] = r4[1];
                bfr[2 * jt + 1][0] = r4[2]; bfr[2 * jt + 1][1] = r4[3];
            }
            // A frags + MMA
            #pragma unroll
            for (int mi = 0; mi < 4; mi++) {
                const int r = a_row + mi * 16;
                const int ch = ks * 2 + a_half;
                uint32_t a4[4];
                ldsm_x4(a4, abase + r * 128 + ((ch ^ (r & 7)) << 4));
                #pragma unroll
                for (int ni = 0; ni < 8; ni++)
                    mma16816(acc[mi][ni], a4, bfr[ni][0], bfr[ni][1]);
            }
        }

        if (it + STAGES - 1 < KT) load_stage(it + STAGES - 1, (it + STAGES - 1) % STAGES);
        else asm volatile("cp.async.commit_group;" ::: "memory");
    }

    // ---- epilogue: streaming float2 stores (out never re-read) ----
    const int er = lane >> 2;
    const int ec = (lane & 3) * 2;
    #pragma unroll
    for (int mi = 0; mi < 4; mi++) {
        #pragma unroll
        for (int ni = 0; ni < 8; ni++) {
            const int row = m0 + warp_m * 64 + mi * 16 + er;
            const int col = n0 + warp_n * 64 + ni * 8 + ec;
            float2 v0 = make_float2(acc[mi][ni][0], acc[mi][ni][1]);
            float2 v1 = make_float2(acc[mi][ni][2], acc[mi][ni][3]);
            __stcs((float2*)&out[(size_t)row * N_DIM + col], v0);
            __stcs((float2*)&out[(size_t)(row + 8) * N_DIM + col], v1);
        }
    }
}

// ---------------------------------------------------------------------------
// Launch
// ---------------------------------------------------------------------------
extern "C" void kernel_launch(void* const* d_in, const int* in_sizes, int n_in,
                              void* d_out, int out_size) {
    const float* x = (const float*)d_in[0];   // [8192, 4096]
    const float* w = (const float*)d_in[1];   // [4096, 4096]
    float* out = (float*)d_out;               // [8192, 4096]

    cudaFuncSetAttribute(k_gemm, cudaFuncAttributeMaxDynamicSharedMemorySize, SMEM_TOTAL);

    k_abs<<<ABS_BLOCKS, 256>>>(w);                      // w -> L2-resident
    k_prep2<<<QUANT_BLOCKS + CONV_BLOCKS, 256>>>(w, x); // quant (L2-hot) + convert

    // N-blocks fast: a concurrent wave shares q (32 MB, L2-resident)
    dim3 grid(N_DIM / BN, M_DIM / BM);
    k_gemm<<<grid, GEMM_THREADS, SMEM_TOTAL>>>(out);
}

// round 17
// speedup vs baseline: 1.0016x; 1.0006x over previous
#include <cuda_runtime.h>
#include <cuda_fp16.h>
#include <cstdint>
#include <cstddef>

// ---------------------------------------------------------------------------
// FINAL (converged, verified 670.5/670.5/670.3/670.1 us): R8 configuration.
//   x -> fp16 (rel_err 2.08e-4, 4.8x under gate), w -> ternary fp16 (exact),
//   GEMM via legacy mma.sync m16n8k16 f16 at the sm_103/compute_103 HMMA floor.
// Session evidence (why nothing else is left):
//   - tcgen05 unreachable: virtual arch compute_103 rejects all "a" features (R1)
//   - int8 legacy IMMA ~6x slower per instruction than HMMA here (R3)
//   - GEMM mainloop floor 612 us: R5 warp-split, R6 stage-depth, R7 reg
//     double-buffer, R13 sync-loader all neutral or worse
//   - prep DRAM floor ~54 us (352 MB): R6/R8/R9/R10/R11 within noise
//   - async g_xh round-trip is load-bearing: removing it cost +290 us (R13)
//   - k_abs is launch/ramp-bound at 14 us: R9 and R15 both neutral/worse
// ---------------------------------------------------------------------------
#define M_DIM 8192
#define N_DIM 4096
#define K_DIM 4096

// GEMM tiling
#define BM 128
#define BN 256
#define BK 64                    // fp16 elems per K-tile = 128 bytes/row
#define STAGES 4
#define KT (K_DIM / BK)          // 64
#define GEMM_THREADS 256         // 8 warps: 2 (M) x 4 (N), warp tile 64x64

#define A_TILE_BYTES (BM * 128)                    // 16 KB
#define B_TILE_BYTES (BN * 128)                    // 32 KB
#define STAGE_BYTES  (A_TILE_BYTES + B_TILE_BYTES) // 48 KB
#define SMEM_TOTAL   (STAGES * STAGE_BYTES)        // 192 KB

#define ABS_BLOCKS   1024        // k1: |w| partials -> w L2-resident
#define QUANT_BLOCKS 2048        // k2: quantize w first (L2-hot)
#define CONV_BLOCKS  8192        // k2: convert x

// ---------------------------------------------------------------------------
// Device scratch (allocation-free rule: __device__ globals)
// ---------------------------------------------------------------------------
__device__ float g_partials[ABS_BLOCKS];
__device__ __align__(1024) __half g_q [(size_t)N_DIM * K_DIM]; // 32 MB {-1,0,1} exact
__device__ __align__(1024) __half g_xh[(size_t)M_DIM * K_DIM]; // 64 MB x in fp16

// ---------------------------------------------------------------------------
// Helpers
// ---------------------------------------------------------------------------
__device__ __forceinline__ uint32_t smem_u32(const void* p) {
    return (uint32_t)__cvta_generic_to_shared(p);
}

__device__ __forceinline__ void cp16(uint32_t dst, const void* src) {
    asm volatile("cp.async.cg.shared.global [%0], [%1], 16;" :: "r"(dst), "l"(src));
}

__device__ __forceinline__ void ldsm_x4(uint32_t (&r)[4], uint32_t addr) {
    asm volatile("ldmatrix.sync.aligned.m8n8.x4.shared.b16 {%0,%1,%2,%3}, [%4];"
                 : "=r"(r[0]), "=r"(r[1]), "=r"(r[2]), "=r"(r[3]) : "r"(addr));
}

__device__ __forceinline__ void mma16816(float (&c)[4], const uint32_t (&a)[4],
                                         uint32_t b0, uint32_t b1) {
    asm volatile(
        "mma.sync.aligned.m16n8k16.row.col.f32.f16.f16.f32 "
        "{%0,%1,%2,%3}, {%4,%5,%6,%7}, {%8,%9}, {%0,%1,%2,%3};"
        : "+f"(c[0]), "+f"(c[1]), "+f"(c[2]), "+f"(c[3])
        : "r"(a[0]), "r"(a[1]), "r"(a[2]), "r"(a[3]), "r"(b0), "r"(b1));
}

__device__ __forceinline__ uint32_t pack2h(float a, float b) {
    __half2 t = __floats2half2_rn(a, b);
    union { __half2 h; uint32_t u; } cv;
    cv.h = t;
    return cv.u;
}

// ---------------------------------------------------------------------------
// k1: |w| partial sums only (leaves w L2-resident: 64 MB < 126 MB L2)
// ---------------------------------------------------------------------------
__global__ void k_abs(const float* __restrict__ w) {
    const float4* w4 = (const float4*)w;
    const int n4 = (N_DIM * K_DIM) / 4;
    float s = 0.0f;
    for (int i = blockIdx.x * blockDim.x + threadIdx.x; i < n4;
         i += ABS_BLOCKS * blockDim.x) {
        float4 v = w4[i];
        s += fabsf(v.x) + fabsf(v.y) + fabsf(v.z) + fabsf(v.w);
    }
    __shared__ float sm[256];
    sm[threadIdx.x] = s;
    __syncthreads();
    for (int o = 128; o > 0; o >>= 1) {
        if (threadIdx.x < o) sm[threadIdx.x] += sm[threadIdx.x + o];
        __syncthreads();
    }
    if (threadIdx.x == 0) g_partials[blockIdx.x] = sm[0];
}

// ---------------------------------------------------------------------------
// k2: blocks [0,QUANT_BLOCKS) re-reduce partials (deterministic fixed-order
//     tree, identical per block), then quantize w -> fp16 {-1,0,1} while w is
//     still L2-hot. blocks [QUANT_BLOCKS,+CONV_BLOCKS) convert x -> fp16.
// ---------------------------------------------------------------------------
__global__ void k_prep2(const float* __restrict__ w, const float* __restrict__ x) {
    if (blockIdx.x < QUANT_BLOCKS) {
        __shared__ float sm[256];
        {
            float s = 0.0f;
            #pragma unroll
            for (int j = 0; j < ABS_BLOCKS / 256; j++)
                s += g_partials[threadIdx.x * (ABS_BLOCKS / 256) + j];
            sm[threadIdx.x] = s;
            __syncthreads();
            for (int o = 128; o > 0; o >>= 1) {
                if (threadIdx.x < o) sm[threadIdx.x] += sm[threadIdx.x + o];
                __syncthreads();
            }
        }
        const float thr = 0.05f * (sm[0] / (float)((size_t)N_DIM * K_DIM));

        const float4* w4 = (const float4*)w;
        uint2* q4 = (uint2*)g_q;
        const int n4 = (N_DIM * K_DIM) / 4;
        auto tq = [&](float v) -> float {
            return v > thr ? 1.0f : (v < -thr ? -1.0f : 0.0f);
        };
        for (int i = blockIdx.x * blockDim.x + threadIdx.x; i < n4;
             i += QUANT_BLOCKS * blockDim.x) {
            float4 v = w4[i];
            uint2 o;
            o.x = pack2h(tq(v.x), tq(v.y));
            o.y = pack2h(tq(v.z), tq(v.w));
            q4[i] = o;
        }
    } else {
        const int bid = blockIdx.x - QUANT_BLOCKS;
        const float4* x4 = (const float4*)x;
        uint2* h4 = (uint2*)g_xh;
        const int n4 = (M_DIM * K_DIM) / 4;
        for (int i = bid * blockDim.x + threadIdx.x; i < n4;
             i += CONV_BLOCKS * blockDim.x) {
            float4 v = x4[i];
            uint2 o;
            o.x = pack2h(v.x, v.y);
            o.y = pack2h(v.z, v.w);
            h4[i] = o;
        }
    }
}

// ---------------------------------------------------------------------------
// GEMM: out = x_fp16 @ q^T via mma.sync m16n8k16 f16 (fp32 accum)
//   CTA tile 128x256, warp tile 64x64, 4-stage cp.async pipeline.
//   Proven floor on this build target — do not touch.
// ---------------------------------------------------------------------------
__global__ void __launch_bounds__(GEMM_THREADS, 1)
k_gemm(float* __restrict__ out) {
    extern __shared__ char smem[];
    const uint32_t sb = smem_u32(smem);
    const int tid  = threadIdx.x;
    const int wid  = tid >> 5;
    const int lane = tid & 31;
    const int warp_m = wid & 1;   // 64 rows each
    const int warp_n = wid >> 1;  // 64 cols each
    const int m0 = blockIdx.y * BM;
    const int n0 = blockIdx.x * BN;

    // ---- async tile loader (XOR-swizzled 16B chunks, 128B rows) ----
    auto load_stage = [&](int kt, int st) {
        const uint32_t base = sb + st * STAGE_BYTES;
        const size_t kofs = (size_t)kt * BK;
        #pragma unroll
        for (int i = tid; i < BM * 8; i += GEMM_THREADS) {
            const int r = i >> 3, c = i & 7;
            const uint32_t d = base + r * 128 + ((c ^ (r & 7)) << 4);
            cp16(d, &g_xh[(size_t)(m0 + r) * K_DIM + kofs + c * 8]);
        }
        #pragma unroll
        for (int i = tid; i < BN * 8; i += GEMM_THREADS) {
            const int r = i >> 3, c = i & 7;
            const uint32_t d = base + A_TILE_BYTES + r * 128 + ((c ^ (r & 7)) << 4);
            cp16(d, &g_q[(size_t)(n0 + r) * K_DIM + kofs + c * 8]);
        }
        asm volatile("cp.async.commit_group;" ::: "memory");
    };

    float acc[4][8][4];   // 128 regs
    #pragma unroll
    for (int mi = 0; mi < 4; mi++)
        #pragma unroll
        for (int ni = 0; ni < 8; ni++)
            #pragma unroll
            for (int j = 0; j < 4; j++) acc[mi][ni][j] = 0.0f;

    // ldmatrix lane addressing (verified layout)
    const int a_row  = warp_m * 64 + (lane & 15);
    const int a_half = lane >> 4;
    const int b_row  = warp_n * 64 + (lane & 7) + ((lane >> 4) << 3);
    const int b_half = (lane >> 3) & 1;

    #pragma unroll
    for (int j = 0; j < STAGES - 1; j++) load_stage(j, j);

    for (int it = 0; it < KT; it++) {
        const int st = it % STAGES;
        asm volatile("cp.async.wait_group %0;" :: "n"(STAGES - 2) : "memory");
        __syncthreads();

        const uint32_t abase = sb + st * STAGE_BYTES;
        const uint32_t bbase = abase + A_TILE_BYTES;

        #pragma unroll
        for (int ks = 0; ks < 4; ks++) {  // 4 x k16 covers BK=64
            // B frags: 4 ldsm.x4 -> 8 n8-frags
            uint32_t bfr[8][2];
            #pragma unroll
            for (int jt = 0; jt < 4; jt++) {
                const int n = b_row + jt * 16;
                const int ch = ks * 2 + b_half;
                uint32_t r4[4];
                ldsm_x4(r4, bbase + n * 128 + ((ch ^ (n & 7)) << 4));
                bfr[2 * jt + 0][0] = r4[0]; bfr[2 * jt + 0][1] = r4[1];
                bfr[2 * jt + 1][0] = r4[2]; bfr[2 * jt + 1][1] = r4[3];
            }
            // A frags + MMA
            #pragma unroll
            for (int mi = 0; mi < 4; mi++) {
                const int r = a_row + mi * 16;
                const int ch = ks * 2 + a_half;
                uint32_t a4[4];
                ldsm_x4(a4, abase + r * 128 + ((ch ^ (r & 7)) << 4));
                #pragma unroll
                for (int ni = 0; ni < 8; ni++)
                    mma16816(acc[mi][ni], a4, bfr[ni][0], bfr[ni][1]);
            }
        }

        if (it + STAGES - 1 < KT) load_stage(it + STAGES - 1, (it + STAGES - 1) % STAGES);
        else asm volatile("cp.async.commit_group;" ::: "memory");
    }

    // ---- epilogue: streaming float2 stores (out never re-read) ----
    const int er = lane >> 2;
    const int ec = (lane & 3) * 2;
    #pragma unroll
    for (int mi = 0; mi < 4; mi++) {
        #pragma unroll
        for (int ni = 0; ni < 8; ni++) {
            const int row = m0 + warp_m * 64 + mi * 16 + er;
            const int col = n0 + warp_n * 64 + ni * 8 + ec;
            float2 v0 = make_float2(acc[mi][ni][0], acc[mi][ni][1]);
            float2 v1 = make_float2(acc[mi][ni][2], acc[mi][ni][3]);
            __stcs((float2*)&out[(size_t)row * N_DIM + col], v0);
            __stcs((float2*)&out[(size_t)(row + 8) * N_DIM + col], v1);
        }
    }
}

// ---------------------------------------------------------------------------
// Launch
// ---------------------------------------------------------------------------
extern "C" void kernel_launch(void* const* d_in, const int* in_sizes, int n_in,
                              void* d_out, int out_size) {
    const float* x = (const float*)d_in[0];   // [8192, 4096]
    const float* w = (const float*)d_in[1];   // [4096, 4096]
    float* out = (float*)d_out;               // [8192, 4096]

    cudaFuncSetAttribute(k_gemm, cudaFuncAttributeMaxDynamicSharedMemorySize, SMEM_TOTAL);

    k_abs<<<ABS_BLOCKS, 256>>>(w);                      // w -> L2-resident
    k_prep2<<<QUANT_BLOCKS + CONV_BLOCKS, 256>>>(w, x); // quant (L2-hot) + convert

    // N-blocks fast: a concurrent wave shares q (32 MB, L2-resident)
    dim3 grid(N_DIM / BN, M_DIM / BM);
    k_gemm<<<grid, GEMM_THREADS, SMEM_TOTAL>>>(out);
}